// round 6
// baseline (speedup 1.0000x reference)
#include <cuda_runtime.h>

// out = g*(x - trend) + (1-g)*trend = g*x + (1-2g)*trend
// trend[0]=x[0]; trend[l] = 0.7*x[l] + 0.3*trend[l-1]   (per (b,c) sequence)
//
// Parallel decomposition: carry forgotten at rate 0.3/step. SEG=128 segments
// with HALO=16 warm-up (damping 0.3^16 ~ 4.3e-9, below fp32 roundoff).
// seg==0 needs no halo: seeding the carry with x[0] gives t[0] = 0.7x0+0.3x0 = x0.
//
// Main loop is software-pipelined in registers (groups of 4 l-steps,
// prefetch group k+1 before consuming group k) so each warp keeps 4
// LDG.128s in flight continuously instead of stalling between groups.

#define ALPHA 0.7f
#define BETA  0.3f

constexpr int Bdim = 32;
constexpr int Ldim = 4096;
constexpr int Cdim = 512;
constexpr int C4   = Cdim / 4;   // 128 float4 lanes per row
constexpr int SEG  = 128;
constexpr int HALO = 16;
constexpr int NSEG = Ldim / SEG; // 32
constexpr int GRP  = 4;          // l-steps per pipelined group

__global__ __launch_bounds__(C4, 6)
void star_ema_kernel(const float4* __restrict__ x,
                     const float*  __restrict__ gate,
                     float4*       __restrict__ out) {
    const int c4  = threadIdx.x;        // 0..127  (coalesced across warp)
    const int seg = blockIdx.x;         // 0..NSEG-1
    const int b   = blockIdx.y;         // 0..B-1

    float g = gate[0];
    g = fminf(fmaxf(g, 0.0f), 1.0f);
    const float w = 1.0f - 2.0f * g;    // out = g*x + w*trend

    const float4* __restrict__ xb = x   + (size_t)b * Ldim * C4 + c4;
    float4*       __restrict__ ob = out + (size_t)b * Ldim * C4 + c4;

    const int l0 = seg * SEG;
    float4 t;

    if (seg == 0) {
        // seed carry with x[0]: first iteration produces t[0] = x[0] exactly
        t = xb[0];
    } else {
        // halo warm-up (no writes); initial carry error decays by 0.3^HALO
        const int ls = l0 - HALO;
        t = xb[(size_t)ls * C4];
        #pragma unroll
        for (int h = ls + 1; h < l0; ++h) {
            float4 v = xb[(size_t)h * C4];
            t.x = fmaf(BETA, t.x, ALPHA * v.x);
            t.y = fmaf(BETA, t.y, ALPHA * v.y);
            t.z = fmaf(BETA, t.z, ALPHA * v.z);
            t.w = fmaf(BETA, t.w, ALPHA * v.w);
        }
    }

    // ---- software-pipelined main loop over SEG elements in groups of GRP ----
    float4 cur[GRP];
    #pragma unroll
    for (int i = 0; i < GRP; ++i)
        cur[i] = xb[(size_t)(l0 + i) * C4];

    #pragma unroll 2
    for (int lg = l0; lg < l0 + SEG; lg += GRP) {
        // prefetch next group (predicated off for the final group)
        float4 nxt[GRP];
        const int lp = lg + GRP;
        if (lp < l0 + SEG) {
            #pragma unroll
            for (int i = 0; i < GRP; ++i)
                nxt[i] = xb[(size_t)(lp + i) * C4];
        }

        // consume current group
        #pragma unroll
        for (int i = 0; i < GRP; ++i) {
            float4 v = cur[i];
            t.x = fmaf(BETA, t.x, ALPHA * v.x);
            t.y = fmaf(BETA, t.y, ALPHA * v.y);
            t.z = fmaf(BETA, t.z, ALPHA * v.z);
            t.w = fmaf(BETA, t.w, ALPHA * v.w);
            float4 o;
            o.x = fmaf(w, t.x, g * v.x);
            o.y = fmaf(w, t.y, g * v.y);
            o.z = fmaf(w, t.z, g * v.z);
            o.w = fmaf(w, t.w, g * v.w);
            ob[(size_t)(lg + i) * C4] = o;
        }

        #pragma unroll
        for (int i = 0; i < GRP; ++i)
            cur[i] = nxt[i];
    }
}

extern "C" void kernel_launch(void* const* d_in, const int* in_sizes, int n_in,
                              void* d_out, int out_size) {
    const float4* x    = (const float4*)d_in[0];
    const float*  gate = (const float*)d_in[1];
    float4*       out  = (float4*)d_out;

    dim3 grid(NSEG, Bdim);
    dim3 block(C4);
    star_ema_kernel<<<grid, block>>>(x, gate, out);
}

// round 7
// speedup vs baseline: 1.0687x; 1.0687x over previous
#include <cuda_runtime.h>

// out = g*(x - trend) + (1-g)*trend = g*x + (1-2g)*trend
// trend[0]=x[0]; trend[l] = 0.7*x[l] + 0.3*trend[l-1]   (per (b,c) sequence)
//
// Parallel decomposition: the recurrence forgets its carry at rate 0.3/step.
// Segment the L axis (SEG=64) and warm each segment up over a HALO=16 prefix
// starting from t = x[l0-HALO]; carry error is damped by 0.3^16 ≈ 4.3e-9,
// below the chain's own fp32 roundoff. Halo re-reads are L2-absorbed
// (measured: DRAM traffic ~= logical floor at 12.5% halo), so the extra
// redundancy buys occupancy (grid=2048) nearly for free.
//
// R6 lesson: achieved HBM bandwidth here tracks occupancy, not per-warp
// pipelining — keep the simple unroll-4 body (ptxas batches its loads) and
// maximize resident warps.

#define ALPHA 0.7f
#define BETA  0.3f

constexpr int Bdim = 32;
constexpr int Ldim = 4096;
constexpr int Cdim = 512;
constexpr int C4   = Cdim / 4;   // 128 float4 lanes per row
constexpr int SEG  = 64;
constexpr int HALO = 16;
constexpr int NSEG = Ldim / SEG; // 64

__global__ __launch_bounds__(C4, 8)
void star_ema_kernel(const float4* __restrict__ x,
                     const float*  __restrict__ gate,
                     float4*       __restrict__ out) {
    const int c4  = threadIdx.x;        // 0..127  (coalesced across warp)
    const int seg = blockIdx.x;         // 0..NSEG-1
    const int b   = blockIdx.y;         // 0..B-1

    float g = gate[0];
    g = fminf(fmaxf(g, 0.0f), 1.0f);
    const float w = 1.0f - 2.0f * g;    // out = g*x + w*trend

    const float4* __restrict__ xb = x   + (size_t)b * Ldim * C4 + c4;
    float4*       __restrict__ ob = out + (size_t)b * Ldim * C4 + c4;

    const int l0 = seg * SEG;
    float4 t;
    int l;

    if (seg == 0) {
        // exact start: trend[0] = x[0]
        float4 v = xb[0];
        t = v;
        float4 o;
        o.x = fmaf(w, t.x, g * v.x);
        o.y = fmaf(w, t.y, g * v.y);
        o.z = fmaf(w, t.z, g * v.z);
        o.w = fmaf(w, t.w, g * v.w);
        ob[0] = o;
        l = 1;
    } else {
        // halo warm-up (no writes); initial carry error decays by 0.3^HALO
        int ls = l0 - HALO;
        t = xb[(size_t)ls * C4];
        #pragma unroll
        for (int h = ls + 1; h < l0; ++h) {
            float4 v = xb[(size_t)h * C4];
            t.x = fmaf(BETA, t.x, ALPHA * v.x);
            t.y = fmaf(BETA, t.y, ALPHA * v.y);
            t.z = fmaf(BETA, t.z, ALPHA * v.z);
            t.w = fmaf(BETA, t.w, ALPHA * v.w);
        }
        l = l0;
    }

    const int lend = l0 + SEG;
    #pragma unroll 4
    for (; l < lend; ++l) {
        float4 v = xb[(size_t)l * C4];
        t.x = fmaf(BETA, t.x, ALPHA * v.x);
        t.y = fmaf(BETA, t.y, ALPHA * v.y);
        t.z = fmaf(BETA, t.z, ALPHA * v.z);
        t.w = fmaf(BETA, t.w, ALPHA * v.w);
        float4 o;
        o.x = fmaf(w, t.x, g * v.x);
        o.y = fmaf(w, t.y, g * v.y);
        o.z = fmaf(w, t.z, g * v.z);
        o.w = fmaf(w, t.w, g * v.w);
        ob[(size_t)l * C4] = o;
    }
}

extern "C" void kernel_launch(void* const* d_in, const int* in_sizes, int n_in,
                              void* d_out, int out_size) {
    const float4* x    = (const float4*)d_in[0];
    const float*  gate = (const float*)d_in[1];
    float4*       out  = (float4*)d_out;

    dim3 grid(NSEG, Bdim);
    dim3 block(C4);
    star_ema_kernel<<<grid, block>>>(x, gate, out);
}